// round 2
// baseline (speedup 1.0000x reference)
#include <cuda_runtime.h>
#include <math.h>

#define NU 50000
#define NI 50000
#define NN 100000
#define NE 1600000
#define NP 200000
#define H  64

// ---------------- device scratch (no allocations allowed) ----------------
__device__ float g_deg[2 * NN];                 // [0,NN): out_norm, [NN,2NN): in_norm
__device__ float g_e0[(size_t)NN * H];          // relu embeddings (layer-0 input)
__device__ float g_agg0[(size_t)NN * H];        // layer-1 aggregate -> emb1 (in place)
__device__ float g_agg1[(size_t)NN * H];        // layer-2 aggregate (raw)
__device__ float g_up[(size_t)NP * H];          // userE @ W1[0:64]   (+b1)
__device__ float g_pp[(size_t)NP * H];          // posE  @ W1[64:128]
__device__ float g_np[(size_t)NP * H];          // negE  @ W1[64:128]

// ---------------- zeroing (grid-stride, float4) ----------------
__global__ void clear_kernel() {
    size_t stride = (size_t)gridDim.x * blockDim.x;
    size_t i0 = (size_t)blockIdx.x * blockDim.x + threadIdx.x;
    float4 z = make_float4(0.f, 0.f, 0.f, 0.f);
    for (size_t i = i0; i < (2 * NN) / 4; i += stride) ((float4*)g_deg)[i] = z;
    size_t na = (size_t)NN * H / 4;
    for (size_t i = i0; i < na; i += stride) {
        ((float4*)g_agg0)[i] = z;
        ((float4*)g_agg1)[i] = z;
    }
}

// ---------------- degrees & normalization ----------------
__global__ void degree_kernel(const int* __restrict__ src, const int* __restrict__ dst) {
    int e = blockIdx.x * blockDim.x + threadIdx.x;
    if (e < NE) {
        atomicAdd(&g_deg[src[e]], 1.0f);
        atomicAdd(&g_deg[NN + dst[e]], 1.0f);
    }
}

__global__ void norm_kernel() {
    int i = blockIdx.x * blockDim.x + threadIdx.x;
    if (i < 2 * NN) g_deg[i] = rsqrtf(fmaxf(g_deg[i], 1.0f));
}

// ---------------- generic small-N SGEMM: C[M x 64] = gather(A)[M x K] @ W[K x 64] ----------------
// 64x64 tile per block, 256 threads, 4x4 register tile, K-tile = 16.
__global__ void gemm64_kernel(const float* __restrict__ A, const int* __restrict__ idx,
                              const float* __restrict__ W, const float* __restrict__ bias,
                              float* __restrict__ C, int M, int K, int doRelu) {
    __shared__ float As[16][68];
    __shared__ float Bs[16][68];

    int t  = threadIdx.x;
    int tx = t & 15;    // col group -> cols tx*4 .. tx*4+3
    int ty = t >> 4;    // row group -> rows ty*4 .. ty*4+3
    int bm0 = blockIdx.x * 64;

    // A-tile load mapping: each thread loads one float4 (row ar, k-quad akq)
    int ar  = t >> 2;   // 0..63
    int akq = t & 3;    // 0..3
    int aRow = bm0 + ar;
    bool aValid = aRow < M;
    size_t srcRow = 0;
    if (aValid) srcRow = idx ? (size_t)idx[aRow] : (size_t)aRow;

    // B-tile load mapping
    int bk = t >> 4;    // 0..15 (k within tile)
    int bc = t & 15;    // 0..15 (col quad)

    float acc[4][4];
#pragma unroll
    for (int i = 0; i < 4; i++)
#pragma unroll
        for (int j = 0; j < 4; j++) acc[i][j] = 0.f;

    for (int k0 = 0; k0 < K; k0 += 16) {
        float4 av = make_float4(0.f, 0.f, 0.f, 0.f);
        if (aValid) av = *(const float4*)(A + srcRow * K + k0 + akq * 4);
        float4 bv = *(const float4*)(W + (size_t)(k0 + bk) * 64 + bc * 4);

        __syncthreads();
        As[akq * 4 + 0][ar] = av.x;
        As[akq * 4 + 1][ar] = av.y;
        As[akq * 4 + 2][ar] = av.z;
        As[akq * 4 + 3][ar] = av.w;
        *(float4*)&Bs[bk][bc * 4] = bv;
        __syncthreads();

#pragma unroll
        for (int k = 0; k < 16; k++) {
            float4 a = *(const float4*)&As[k][ty * 4];
            float4 b = *(const float4*)&Bs[k][tx * 4];
            acc[0][0] += a.x * b.x; acc[0][1] += a.x * b.y; acc[0][2] += a.x * b.z; acc[0][3] += a.x * b.w;
            acc[1][0] += a.y * b.x; acc[1][1] += a.y * b.y; acc[1][2] += a.y * b.z; acc[1][3] += a.y * b.w;
            acc[2][0] += a.z * b.x; acc[2][1] += a.z * b.y; acc[2][2] += a.z * b.z; acc[2][3] += a.z * b.w;
            acc[3][0] += a.w * b.x; acc[3][1] += a.w * b.y; acc[3][2] += a.w * b.z; acc[3][3] += a.w * b.w;
        }
    }

    float bvals[4] = {0.f, 0.f, 0.f, 0.f};
    if (bias) {
#pragma unroll
        for (int j = 0; j < 4; j++) bvals[j] = bias[tx * 4 + j];
    }

#pragma unroll
    for (int i = 0; i < 4; i++) {
        int row = bm0 + ty * 4 + i;
        if (row < M) {
            float4 v;
            v.x = acc[i][0] + bvals[0];
            v.y = acc[i][1] + bvals[1];
            v.z = acc[i][2] + bvals[2];
            v.w = acc[i][3] + bvals[3];
            if (doRelu) {
                v.x = fmaxf(v.x, 0.f); v.y = fmaxf(v.y, 0.f);
                v.z = fmaxf(v.z, 0.f); v.w = fmaxf(v.w, 0.f);
            }
            *(float4*)(C + (size_t)row * 64 + tx * 4) = v;
        }
    }
}

// ---------------- GCN scatter: out[dst] += src_vals[src] * out_norm[src] ----------------
// one thread per (edge, float4-chunk); float4 atomics (RED.128)
__global__ void scatter_kernel(const float* __restrict__ sv, float* __restrict__ out,
                               const int* __restrict__ es, const int* __restrict__ ed) {
    unsigned gid = blockIdx.x * blockDim.x + threadIdx.x;
    if (gid >= (unsigned)NE * 16u) return;
    unsigned e = gid >> 4, f = gid & 15u;
    int s = es[e], d = ed[e];
    float sc = g_deg[s];
    float4 v = ((const float4*)sv)[(size_t)s * 16 + f];
    float4 r = make_float4(v.x * sc, v.y * sc, v.z * sc, v.w * sc);
    atomicAdd(((float4*)out) + (size_t)d * 16 + f, r);
}

// a[node] *= in_norm[node]   (float4 granularity)
__global__ void innorm_kernel(float* __restrict__ a) {
    int i = blockIdx.x * blockDim.x + threadIdx.x;
    if (i < NN * 16) {
        float sc = g_deg[NN + (i >> 4)];
        float4 v = ((float4*)a)[i];
        ((float4*)a)[i] = make_float4(v.x * sc, v.y * sc, v.z * sc, v.w * sc);
    }
}

// ---------------- finalize embeddings into d_out ----------------
__global__ void final_user_kernel(float* __restrict__ out) {
    int i = blockIdx.x * blockDim.x + threadIdx.x;
    if (i < NU * 16) {
        int node = i >> 4;
        float s3 = g_deg[NN + node] * (1.0f / 3.0f);
        float4 e  = ((const float4*)g_e0)[i];
        float4 a0 = ((const float4*)g_agg0)[i];   // already = emb1
        float4 a1 = ((const float4*)g_agg1)[i];   // raw, needs in_norm
        float4 r;
        r.x = e.x + 0.5f * a0.x + s3 * a1.x;
        r.y = e.y + 0.5f * a0.y + s3 * a1.y;
        r.z = e.z + 0.5f * a0.z + s3 * a1.z;
        r.w = e.w + 0.5f * a0.w + s3 * a1.w;
        ((float4*)out)[i] = r;
    }
}

__global__ void final_item_kernel(const float* __restrict__ side, float* __restrict__ out) {
    int i = blockIdx.x * blockDim.x + threadIdx.x;
    if (i < NI * 16) {
        int node = NU + (i >> 4);
        size_t gi = (size_t)NU * 16 + i;
        float s3 = g_deg[NN + node] * (1.0f / 3.0f);
        float4 e  = ((const float4*)g_e0)[gi];
        float4 a0 = ((const float4*)g_agg0)[gi];
        float4 a1 = ((const float4*)g_agg1)[gi];
        float4 sd = ((const float4*)side)[i];
        float4 r;
        r.x = e.x + 0.5f * a0.x + s3 * a1.x + sd.x;
        r.y = e.y + 0.5f * a0.y + s3 * a1.y + sd.y;
        r.z = e.z + 0.5f * a0.z + s3 * a1.z + sd.z;
        r.w = e.w + 0.5f * a0.w + s3 * a1.w + sd.w;
        ((float4*)out)[gi] = r;
    }
}

// ---------------- decode epilogue: elu + dot(W2), 4 logits per pair ----------------
__global__ void decode_kernel(const float* __restrict__ Tf, const float* __restrict__ Tcf,
                              const float* __restrict__ W1, const float* __restrict__ W2,
                              float* __restrict__ of, float* __restrict__ ocf) {
    __shared__ float w2s[64];
    __shared__ float w1l[64];
    int t = threadIdx.x;
    if (t < 64) {
        w2s[t] = W2[t];
        w1l[t] = W1[128 * 64 + t];   // last row of W1 (T coefficient)
    }
    __syncthreads();

    int warp = t >> 5, lane = t & 31;
    int pair = blockIdx.x * 4 + warp;
    if (pair >= NP) return;

    const float* up  = g_up + (size_t)pair * 64;
    const float* pp  = g_pp + (size_t)pair * 64;
    const float* npp = g_np + (size_t)pair * 64;
    float u0 = up[lane],  u1 = up[lane + 32];
    float p0 = pp[lane],  p1 = pp[lane + 32];
    float n0 = npp[lane], n1 = npp[lane + 32];
    float wl0 = w1l[lane], wl1 = w1l[lane + 32];
    float w20 = w2s[lane], w21 = w2s[lane + 32];

    float tfp = Tf[pair],  tfn = Tf[pair + NP];
    float tcp = Tcf[pair], tcn = Tcf[pair + NP];

    auto combo = [&](float j0, float j1, float T) -> float {
        float x0 = u0 + j0 + T * wl0;
        float x1 = u1 + j1 + T * wl1;
        float e0 = x0 > 0.f ? x0 : (expf(x0) - 1.0f);
        float e1 = x1 > 0.f ? x1 : (expf(x1) - 1.0f);
        float s = e0 * w20 + e1 * w21;
        s += __shfl_down_sync(0xffffffffu, s, 16);
        s += __shfl_down_sync(0xffffffffu, s, 8);
        s += __shfl_down_sync(0xffffffffu, s, 4);
        s += __shfl_down_sync(0xffffffffu, s, 2);
        s += __shfl_down_sync(0xffffffffu, s, 1);
        return s;
    };

    float rf_p = combo(p0, p1, tfp);
    float rf_n = combo(n0, n1, tfn);
    float rc_p = combo(p0, p1, tcp);
    float rc_n = combo(n0, n1, tcn);

    if (lane == 0) {
        of[pair]       = rf_p;
        of[pair + NP]  = rf_n;
        ocf[pair]      = rc_p;
        ocf[pair + NP] = rc_n;
    }
}

// ---------------- launch ----------------
extern "C" void kernel_launch(void* const* d_in, const int* in_sizes, int n_in,
                              void* d_out, int out_size) {
    const float* userF = (const float*)d_in[0];
    const float* itemF = (const float*)d_in[1];
    const float* side  = (const float*)d_in[2];
    const float* Tf    = (const float*)d_in[3];
    const float* Tcf   = (const float*)d_in[4];
    const float* Wu    = (const float*)d_in[5];
    const float* bu    = (const float*)d_in[6];
    const float* Wi    = (const float*)d_in[7];
    const float* bi    = (const float*)d_in[8];
    const float* W1    = (const float*)d_in[9];
    const float* b1    = (const float*)d_in[10];
    const float* W2    = (const float*)d_in[11];
    const int* esrc    = (const int*)d_in[12];
    const int* edst    = (const int*)d_in[13];
    const int* userId  = (const int*)d_in[14];
    const int* posId   = (const int*)d_in[15];
    const int* negId   = (const int*)d_in[16];

    float* out   = (float*)d_out;
    float* outI  = out + (size_t)NU * H;           // item embeddings
    float* outLF = out + (size_t)NN * H;           // logits_f
    float* outLC = outLF + 2 * NP;                 // logits_cf

    float *pe0, *pagg0, *pagg1, *pup, *ppp, *pnp;
    cudaGetSymbolAddress((void**)&pe0,   g_e0);
    cudaGetSymbolAddress((void**)&pagg0, g_agg0);
    cudaGetSymbolAddress((void**)&pagg1, g_agg1);
    cudaGetSymbolAddress((void**)&pup,   g_up);
    cudaGetSymbolAddress((void**)&ppp,   g_pp);
    cudaGetSymbolAddress((void**)&pnp,   g_np);

    // 1. clear scratch
    clear_kernel<<<2048, 256>>>();

    // 2. degrees + norms
    degree_kernel<<<(NE + 255) / 256, 256>>>(esrc, edst);
    norm_kernel<<<(2 * NN + 255) / 256, 256>>>();

    // 3. input embeddings (relu(X @ W + b))
    gemm64_kernel<<<(NU + 63) / 64, 256>>>(userF, nullptr, Wu, bu, pe0, NU, 128, 1);
    gemm64_kernel<<<(NI + 63) / 64, 256>>>(itemF, nullptr, Wi, bi, pe0 + (size_t)NU * H, NI, 128, 1);

    // 4. GCN layer 1
    scatter_kernel<<<(NE * 16 + 255) / 256, 256>>>(pe0, pagg0, esrc, edst);
    innorm_kernel<<<(NN * 16 + 255) / 256, 256>>>(pagg0);   // agg0 -> emb1

    // 5. GCN layer 2
    scatter_kernel<<<(NE * 16 + 255) / 256, 256>>>(pagg0, pagg1, esrc, edst);

    // 6. finalize embeddings into d_out
    final_user_kernel<<<(NU * 16 + 255) / 256, 256>>>(out);
    final_item_kernel<<<(NI * 16 + 255) / 256, 256>>>(side, out);

    // 7. decode GEMMs (gathered), factored: u-part(+b1), pos-part, neg-part
    gemm64_kernel<<<(NP + 63) / 64, 256>>>(out,  userId, W1,            b1,      pup, NP, 64, 0);
    gemm64_kernel<<<(NP + 63) / 64, 256>>>(outI, posId,  W1 + 64 * 64, nullptr, ppp, NP, 64, 0);
    gemm64_kernel<<<(NP + 63) / 64, 256>>>(outI, negId,  W1 + 64 * 64, nullptr, pnp, NP, 64, 0);

    // 8. decode epilogue -> logits
    decode_kernel<<<(NP + 3) / 4, 128>>>(Tf, Tcf, W1, W2, outLF, outLC);
}

// round 3
// speedup vs baseline: 1.6382x; 1.6382x over previous
#include <cuda_runtime.h>
#include <math.h>

#define NU 50000
#define NI 50000
#define NN 100000
#define NE 1600000
#define NP 200000
#define H  64
#define SCAN_NBLK ((NN + 1023) / 1024)   // 98

// ---------------- device scratch ----------------
__device__ int   g_ocnt[NN];                    // out-degree (int)
__device__ int   g_icnt[NN];                    // in-degree (int)
__device__ float g_onorm[NN];                   // out_deg^-1/2
__device__ float g_innorm[NN];                  // in_deg^-1/2
__device__ int   g_off[NN];                     // CSR offsets (by dst)
__device__ int   g_cur[NN];                     // fill cursors
__device__ int   g_bsum[SCAN_NBLK];
__device__ int   g_boff[SCAN_NBLK];
__device__ int   g_csrc[NE];                    // src ids sorted by dst
__device__ float g_e0[(size_t)NN * H];          // relu embeddings
__device__ float g_agg0[(size_t)NN * H];        // layer-1 output ("embeddings")
__device__ float g_xu[(size_t)NU * H];          // user_emb_final @ W1[0:64] + b1
__device__ float g_xi[(size_t)NI * H];          // item_emb_final @ W1[64:128]

// ---------------- clear counters ----------------
__global__ void clear_kernel() {
    int i = blockIdx.x * blockDim.x + threadIdx.x;
    if (i < NN) { g_ocnt[i] = 0; g_icnt[i] = 0; }
}

// ---------------- degrees ----------------
__global__ void degree_kernel(const int* __restrict__ src, const int* __restrict__ dst) {
    int e = blockIdx.x * blockDim.x + threadIdx.x;
    if (e < NE) {
        atomicAdd(&g_ocnt[src[e]], 1);
        atomicAdd(&g_icnt[dst[e]], 1);
    }
}

__global__ void norm_kernel() {
    int i = blockIdx.x * blockDim.x + threadIdx.x;
    if (i < NN) {
        g_onorm[i]  = rsqrtf(fmaxf((float)g_ocnt[i], 1.0f));
        g_innorm[i] = rsqrtf(fmaxf((float)g_icnt[i], 1.0f));
    }
}

// ---------------- 3-step scan of in-degrees -> CSR offsets ----------------
__global__ void scan1_kernel() {
    __shared__ int sh[1024];
    int tid = threadIdx.x;
    int i = blockIdx.x * 1024 + tid;
    int v = (i < NN) ? g_icnt[i] : 0;
    sh[tid] = v;
    __syncthreads();
#pragma unroll
    for (int off = 1; off < 1024; off <<= 1) {
        int t = (tid >= off) ? sh[tid - off] : 0;
        __syncthreads();
        sh[tid] += t;
        __syncthreads();
    }
    if (i < NN) g_off[i] = sh[tid] - v;          // exclusive
    if (tid == 1023) g_bsum[blockIdx.x] = sh[1023];
}

__global__ void scan2_kernel() {
    __shared__ int sh[128];
    int tid = threadIdx.x;
    int v = (tid < SCAN_NBLK) ? g_bsum[tid] : 0;
    sh[tid] = v;
    __syncthreads();
#pragma unroll
    for (int off = 1; off < 128; off <<= 1) {
        int t = (tid >= off) ? sh[tid - off] : 0;
        __syncthreads();
        sh[tid] += t;
        __syncthreads();
    }
    if (tid < SCAN_NBLK) g_boff[tid] = sh[tid] - v;
}

__global__ void scan3_kernel() {
    int i = blockIdx.x * blockDim.x + threadIdx.x;
    if (i < NN) {
        int o = g_off[i] + g_boff[i >> 10];
        g_off[i] = o;
        g_cur[i] = o;
    }
}

__global__ void fill_kernel(const int* __restrict__ src, const int* __restrict__ dst) {
    int e = blockIdx.x * blockDim.x + threadIdx.x;
    if (e < NE) {
        int pos = atomicAdd(&g_cur[dst[e]], 1);
        g_csrc[pos] = src[e];
    }
}

// ---------------- generic small-N SGEMM: C[M x 64] = A[M x K] @ W[K x 64] ----------------
__global__ void gemm64_kernel(const float* __restrict__ A,
                              const float* __restrict__ W, const float* __restrict__ bias,
                              float* __restrict__ C, int M, int K, int doRelu) {
    __shared__ float As[16][68];
    __shared__ float Bs[16][68];

    int t  = threadIdx.x;
    int tx = t & 15;
    int ty = t >> 4;
    int bm0 = blockIdx.x * 64;

    int ar  = t >> 2;
    int akq = t & 3;
    int aRow = bm0 + ar;
    bool aValid = aRow < M;

    int bk = t >> 4;
    int bc = t & 15;

    float acc[4][4];
#pragma unroll
    for (int i = 0; i < 4; i++)
#pragma unroll
        for (int j = 0; j < 4; j++) acc[i][j] = 0.f;

    for (int k0 = 0; k0 < K; k0 += 16) {
        float4 av = make_float4(0.f, 0.f, 0.f, 0.f);
        if (aValid) av = *(const float4*)(A + (size_t)aRow * K + k0 + akq * 4);
        float4 bv = *(const float4*)(W + (size_t)(k0 + bk) * 64 + bc * 4);

        __syncthreads();
        As[akq * 4 + 0][ar] = av.x;
        As[akq * 4 + 1][ar] = av.y;
        As[akq * 4 + 2][ar] = av.z;
        As[akq * 4 + 3][ar] = av.w;
        *(float4*)&Bs[bk][bc * 4] = bv;
        __syncthreads();

#pragma unroll
        for (int k = 0; k < 16; k++) {
            float4 a = *(const float4*)&As[k][ty * 4];
            float4 b = *(const float4*)&Bs[k][tx * 4];
            acc[0][0] += a.x * b.x; acc[0][1] += a.x * b.y; acc[0][2] += a.x * b.z; acc[0][3] += a.x * b.w;
            acc[1][0] += a.y * b.x; acc[1][1] += a.y * b.y; acc[1][2] += a.y * b.z; acc[1][3] += a.y * b.w;
            acc[2][0] += a.z * b.x; acc[2][1] += a.z * b.y; acc[2][2] += a.z * b.z; acc[2][3] += a.z * b.w;
            acc[3][0] += a.w * b.x; acc[3][1] += a.w * b.y; acc[3][2] += a.w * b.z; acc[3][3] += a.w * b.w;
        }
    }

    float bvals[4] = {0.f, 0.f, 0.f, 0.f};
    if (bias) {
#pragma unroll
        for (int j = 0; j < 4; j++) bvals[j] = bias[tx * 4 + j];
    }

#pragma unroll
    for (int i = 0; i < 4; i++) {
        int row = bm0 + ty * 4 + i;
        if (row < M) {
            float4 v;
            v.x = acc[i][0] + bvals[0];
            v.y = acc[i][1] + bvals[1];
            v.z = acc[i][2] + bvals[2];
            v.w = acc[i][3] + bvals[3];
            if (doRelu) {
                v.x = fmaxf(v.x, 0.f); v.y = fmaxf(v.y, 0.f);
                v.z = fmaxf(v.z, 0.f); v.w = fmaxf(v.w, 0.f);
            }
            *(float4*)(C + (size_t)row * 64 + tx * 4) = v;
        }
    }
}

// ---------------- GCN layer 1: gather (warp per node) ----------------
// agg0[n] = in_norm[n] * sum_{e: dst=n} e0[src_e] * out_norm[src_e]
__global__ void gather1_kernel() {
    int gw = (blockIdx.x * blockDim.x + threadIdx.x) >> 5;
    int lane = threadIdx.x & 31;
    if (gw >= NN) return;
    int start = g_off[gw];
    int deg = g_icnt[gw];
    float a0 = 0.f, a1 = 0.f;
    int j = 0;
    for (; j + 1 < deg; j += 2) {
        int s0 = g_csrc[start + j];
        int s1 = g_csrc[start + j + 1];
        float w0 = g_onorm[s0], w1 = g_onorm[s1];
        const float* r0 = g_e0 + (size_t)s0 * 64;
        const float* r1 = g_e0 + (size_t)s1 * 64;
        a0 += w0 * r0[lane]      + w1 * r1[lane];
        a1 += w0 * r0[lane + 32] + w1 * r1[lane + 32];
    }
    if (j < deg) {
        int s0 = g_csrc[start + j];
        float w0 = g_onorm[s0];
        const float* r0 = g_e0 + (size_t)s0 * 64;
        a0 += w0 * r0[lane];
        a1 += w0 * r0[lane + 32];
    }
    float inn = g_innorm[gw];
    g_agg0[(size_t)gw * 64 + lane]      = a0 * inn;
    g_agg0[(size_t)gw * 64 + lane + 32] = a1 * inn;
}

// ---------------- GCN layer 2 + final combine fused ----------------
// out[n] = e0[n] + 0.5*agg0[n] + (1/3)*in_norm[n]*sum(agg0[src]*out_norm[src]) (+side for items)
__global__ void gather2_final_kernel(const float* __restrict__ side, float* __restrict__ out) {
    int gw = (blockIdx.x * blockDim.x + threadIdx.x) >> 5;
    int lane = threadIdx.x & 31;
    if (gw >= NN) return;
    int start = g_off[gw];
    int deg = g_icnt[gw];
    float a0 = 0.f, a1 = 0.f;
    int j = 0;
    for (; j + 1 < deg; j += 2) {
        int s0 = g_csrc[start + j];
        int s1 = g_csrc[start + j + 1];
        float w0 = g_onorm[s0], w1 = g_onorm[s1];
        const float* r0 = g_agg0 + (size_t)s0 * 64;
        const float* r1 = g_agg0 + (size_t)s1 * 64;
        a0 += w0 * r0[lane]      + w1 * r1[lane];
        a1 += w0 * r0[lane + 32] + w1 * r1[lane + 32];
    }
    if (j < deg) {
        int s0 = g_csrc[start + j];
        float w0 = g_onorm[s0];
        const float* r0 = g_agg0 + (size_t)s0 * 64;
        a0 += w0 * r0[lane];
        a1 += w0 * r0[lane + 32];
    }
    float inn3 = g_innorm[gw] * (1.0f / 3.0f);
    size_t base = (size_t)gw * 64;
    float r0v = g_e0[base + lane]      + 0.5f * g_agg0[base + lane]      + inn3 * a0;
    float r1v = g_e0[base + lane + 32] + 0.5f * g_agg0[base + lane + 32] + inn3 * a1;
    if (gw >= NU) {
        size_t sb = (size_t)(gw - NU) * 64;
        r0v += side[sb + lane];
        r1v += side[sb + lane + 32];
    }
    out[base + lane]      = r0v;
    out[base + lane + 32] = r1v;
}

// ---------------- decode epilogue: gather xu/xi rows, elu + dot(W2) ----------------
__global__ void decode_kernel(const float* __restrict__ Tf, const float* __restrict__ Tcf,
                              const float* __restrict__ W1, const float* __restrict__ W2,
                              const int* __restrict__ userId, const int* __restrict__ posId,
                              const int* __restrict__ negId,
                              float* __restrict__ of, float* __restrict__ ocf) {
    __shared__ float w2s[64];
    __shared__ float w1l[64];
    int t = threadIdx.x;
    if (t < 64) {
        w2s[t] = W2[t];
        w1l[t] = W1[128 * 64 + t];   // last row of W1 (T coefficient)
    }
    __syncthreads();

    int warp = t >> 5, lane = t & 31;
    int pair = blockIdx.x * 4 + warp;
    if (pair >= NP) return;

    int u  = userId[pair];
    int p  = posId[pair];
    int ng = negId[pair];

    float u0 = g_xu[(size_t)u * 64 + lane],   u1 = g_xu[(size_t)u * 64 + lane + 32];
    float p0 = g_xi[(size_t)p * 64 + lane],   p1 = g_xi[(size_t)p * 64 + lane + 32];
    float n0 = g_xi[(size_t)ng * 64 + lane],  n1 = g_xi[(size_t)ng * 64 + lane + 32];
    float wl0 = w1l[lane], wl1 = w1l[lane + 32];
    float w20 = w2s[lane], w21 = w2s[lane + 32];

    float tfp = Tf[pair],  tfn = Tf[pair + NP];
    float tcp = Tcf[pair], tcn = Tcf[pair + NP];

    auto combo = [&](float j0, float j1, float T) -> float {
        float x0 = u0 + j0 + T * wl0;
        float x1 = u1 + j1 + T * wl1;
        float e0 = x0 > 0.f ? x0 : (expf(x0) - 1.0f);
        float e1 = x1 > 0.f ? x1 : (expf(x1) - 1.0f);
        float s = e0 * w20 + e1 * w21;
        s += __shfl_down_sync(0xffffffffu, s, 16);
        s += __shfl_down_sync(0xffffffffu, s, 8);
        s += __shfl_down_sync(0xffffffffu, s, 4);
        s += __shfl_down_sync(0xffffffffu, s, 2);
        s += __shfl_down_sync(0xffffffffu, s, 1);
        return s;
    };

    float rf_p = combo(p0, p1, tfp);
    float rf_n = combo(n0, n1, tfn);
    float rc_p = combo(p0, p1, tcp);
    float rc_n = combo(n0, n1, tcn);

    if (lane == 0) {
        of[pair]       = rf_p;
        of[pair + NP]  = rf_n;
        ocf[pair]      = rc_p;
        ocf[pair + NP] = rc_n;
    }
}

// ---------------- launch ----------------
extern "C" void kernel_launch(void* const* d_in, const int* in_sizes, int n_in,
                              void* d_out, int out_size) {
    const float* userF = (const float*)d_in[0];
    const float* itemF = (const float*)d_in[1];
    const float* side  = (const float*)d_in[2];
    const float* Tf    = (const float*)d_in[3];
    const float* Tcf   = (const float*)d_in[4];
    const float* Wu    = (const float*)d_in[5];
    const float* bu    = (const float*)d_in[6];
    const float* Wi    = (const float*)d_in[7];
    const float* bi    = (const float*)d_in[8];
    const float* W1    = (const float*)d_in[9];
    const float* b1    = (const float*)d_in[10];
    const float* W2    = (const float*)d_in[11];
    const int* esrc    = (const int*)d_in[12];
    const int* edst    = (const int*)d_in[13];
    const int* userId  = (const int*)d_in[14];
    const int* posId   = (const int*)d_in[15];
    const int* negId   = (const int*)d_in[16];

    float* out   = (float*)d_out;
    float* outI  = out + (size_t)NU * H;
    float* outLF = out + (size_t)NN * H;
    float* outLC = outLF + 2 * NP;

    float *pe0, *pxu, *pxi;
    cudaGetSymbolAddress((void**)&pe0, g_e0);
    cudaGetSymbolAddress((void**)&pxu, g_xu);
    cudaGetSymbolAddress((void**)&pxi, g_xi);

    // CSR + norms
    clear_kernel<<<(NN + 255) / 256, 256>>>();
    degree_kernel<<<(NE + 255) / 256, 256>>>(esrc, edst);
    norm_kernel<<<(NN + 255) / 256, 256>>>();
    scan1_kernel<<<SCAN_NBLK, 1024>>>();
    scan2_kernel<<<1, 128>>>();
    scan3_kernel<<<(NN + 255) / 256, 256>>>();
    fill_kernel<<<(NE + 255) / 256, 256>>>(esrc, edst);

    // input embeddings
    gemm64_kernel<<<(NU + 63) / 64, 256>>>(userF, Wu, bu, pe0, NU, 128, 1);
    gemm64_kernel<<<(NI + 63) / 64, 256>>>(itemF, Wi, bi, pe0 + (size_t)NU * H, NI, 128, 1);

    // GCN layers (gather-based), layer-2 fused with final combine
    gather1_kernel<<<(NN * 32 + 255) / 256, 256>>>();
    gather2_final_kernel<<<(NN * 32 + 255) / 256, 256>>>(side, out);

    // per-node decode transforms
    gemm64_kernel<<<(NU + 63) / 64, 256>>>(out,  W1,           b1,      pxu, NU, 64, 0);
    gemm64_kernel<<<(NI + 63) / 64, 256>>>(outI, W1 + 64 * 64, nullptr, pxi, NI, 64, 0);

    // decode epilogue
    decode_kernel<<<(NP + 3) / 4, 128>>>(Tf, Tcf, W1, W2, userId, posId, negId, outLF, outLC);
}

// round 4
// speedup vs baseline: 1.7761x; 1.0842x over previous
#include <cuda_runtime.h>
#include <math.h>

#define NU 50000
#define NI 50000
#define NN 100000
#define NE 1600000
#define NP 200000
#define H  64
#define SCAN_NBLK ((NN + 1023) / 1024)   // 98

// ---------------- device scratch ----------------
__device__ int   g_ocnt[NN];
__device__ int   g_icnt[NN];
__device__ float g_onorm[NN];
__device__ float g_innorm[NN];
__device__ int   g_off[NN];
__device__ int   g_cur[NN];
__device__ int   g_bsum[SCAN_NBLK];
__device__ int   g_boff[SCAN_NBLK];
__device__ int   g_csrc[NE];
__device__ float g_e0[(size_t)NN * H];
__device__ float g_agg0[(size_t)NN * H];
__device__ float g_xu[(size_t)NU * H];
__device__ float g_xi[(size_t)NI * H];

// ---------------- clear counters ----------------
__global__ void clear_kernel() {
    int i = blockIdx.x * blockDim.x + threadIdx.x;
    if (i < NN) { g_ocnt[i] = 0; g_icnt[i] = 0; }
}

// ---------------- degrees ----------------
__global__ void degree_kernel(const int* __restrict__ src, const int* __restrict__ dst) {
    int e = blockIdx.x * blockDim.x + threadIdx.x;
    if (e < NE) {
        atomicAdd(&g_ocnt[src[e]], 1);
        atomicAdd(&g_icnt[dst[e]], 1);
    }
}

// ---------------- scan of in-degrees -> CSR offsets ----------------
__global__ void scan1_kernel() {
    __shared__ int sh[1024];
    int tid = threadIdx.x;
    int i = blockIdx.x * 1024 + tid;
    int v = (i < NN) ? g_icnt[i] : 0;
    sh[tid] = v;
    __syncthreads();
#pragma unroll
    for (int off = 1; off < 1024; off <<= 1) {
        int t = (tid >= off) ? sh[tid - off] : 0;
        __syncthreads();
        sh[tid] += t;
        __syncthreads();
    }
    if (i < NN) g_off[i] = sh[tid] - v;
    if (tid == 1023) g_bsum[blockIdx.x] = sh[1023];
}

__global__ void scan2_kernel() {
    __shared__ int sh[128];
    int tid = threadIdx.x;
    int v = (tid < SCAN_NBLK) ? g_bsum[tid] : 0;
    sh[tid] = v;
    __syncthreads();
#pragma unroll
    for (int off = 1; off < 128; off <<= 1) {
        int t = (tid >= off) ? sh[tid - off] : 0;
        __syncthreads();
        sh[tid] += t;
        __syncthreads();
    }
    if (tid < SCAN_NBLK) g_boff[tid] = sh[tid] - v;
}

// scan finalize + norms fused
__global__ void scan3_kernel() {
    int i = blockIdx.x * blockDim.x + threadIdx.x;
    if (i < NN) {
        int o = g_off[i] + g_boff[i >> 10];
        g_off[i] = o;
        g_cur[i] = o;
        g_onorm[i]  = rsqrtf(fmaxf((float)g_ocnt[i], 1.0f));
        g_innorm[i] = rsqrtf(fmaxf((float)g_icnt[i], 1.0f));
    }
}

__global__ void fill_kernel(const int* __restrict__ src, const int* __restrict__ dst) {
    int e = blockIdx.x * blockDim.x + threadIdx.x;
    if (e < NE) {
        int pos = atomicAdd(&g_cur[dst[e]], 1);
        g_csrc[pos] = src[e];
    }
}

// ---------------- dual SGEMM: two independent C[M x 64] = A[M x K] @ W[K x 64] ----------------
// 128x64 block tile, 256 threads, 8x4 register tile, whole W in smem, double-buffered A.
__global__ void __launch_bounds__(256) gemm_dual(
    const float* __restrict__ A1, const float* __restrict__ W1, const float* __restrict__ b1,
    float* __restrict__ C1, int M1,
    const float* __restrict__ A2, const float* __restrict__ W2, const float* __restrict__ b2,
    float* __restrict__ C2, int M2,
    int K, int doRelu, int nb1)
{
    __shared__ float Ws[128][64];        // 32KB (K <= 128 rows used)
    __shared__ float As[2][16][128];     // 16KB, [k][row]

    const float* A; const float* W; const float* bias; float* C; int M, bm0;
    if ((int)blockIdx.x < nb1) {
        A = A1; W = W1; bias = b1; C = C1; M = M1; bm0 = blockIdx.x * 128;
    } else {
        A = A2; W = W2; bias = b2; C = C2; M = M2; bm0 = (blockIdx.x - nb1) * 128;
    }

    int t = threadIdx.x;

    // load whole W into smem
    for (int i = t; i < K * 16; i += 256) {
        int k = i >> 4, q = i & 15;
        *(float4*)&Ws[k][q * 4] = *(const float4*)(W + (size_t)k * 64 + q * 4);
    }

    // A staging mapping: 2 threads per row; thread covers k-offsets lq..lq+7 of its row
    int lrow = t >> 1;
    int lq = (t & 1) * 8;
    int row = bm0 + lrow;
    bool rv = row < M;
    const float* Ar = A + (size_t)row * K;

    float4 p0 = make_float4(0.f, 0.f, 0.f, 0.f), p1 = p0;

#define FETCH(k0) do { \
    if (rv) { p0 = *(const float4*)(Ar + (k0) + lq); p1 = *(const float4*)(Ar + (k0) + lq + 4); } \
} while (0)
#define STAGE(buf) do { \
    As[buf][lq + 0][lrow] = p0.x; As[buf][lq + 1][lrow] = p0.y; \
    As[buf][lq + 2][lrow] = p0.z; As[buf][lq + 3][lrow] = p0.w; \
    As[buf][lq + 4][lrow] = p1.x; As[buf][lq + 5][lrow] = p1.y; \
    As[buf][lq + 6][lrow] = p1.z; As[buf][lq + 7][lrow] = p1.w; \
} while (0)

    FETCH(0);
    STAGE(0);
    __syncthreads();

    float acc[8][4];
#pragma unroll
    for (int i = 0; i < 8; i++)
#pragma unroll
        for (int j = 0; j < 4; j++) acc[i][j] = 0.f;

    int tx = t & 15;          // cols tx*4 .. tx*4+3
    int ty = t >> 4;          // rows ty*8 .. ty*8+7
    int nt = K >> 4;

    for (int tile = 0; tile < nt; tile++) {
        int buf = tile & 1;
        if (tile + 1 < nt) FETCH((tile + 1) << 4);

#pragma unroll
        for (int k = 0; k < 16; k++) {
            float4 b  = *(const float4*)&Ws[(tile << 4) + k][tx * 4];
            float4 x0 = *(const float4*)&As[buf][k][ty * 8];
            float4 x1 = *(const float4*)&As[buf][k][ty * 8 + 4];
            acc[0][0] += x0.x * b.x; acc[0][1] += x0.x * b.y; acc[0][2] += x0.x * b.z; acc[0][3] += x0.x * b.w;
            acc[1][0] += x0.y * b.x; acc[1][1] += x0.y * b.y; acc[1][2] += x0.y * b.z; acc[1][3] += x0.y * b.w;
            acc[2][0] += x0.z * b.x; acc[2][1] += x0.z * b.y; acc[2][2] += x0.z * b.z; acc[2][3] += x0.z * b.w;
            acc[3][0] += x0.w * b.x; acc[3][1] += x0.w * b.y; acc[3][2] += x0.w * b.z; acc[3][3] += x0.w * b.w;
            acc[4][0] += x1.x * b.x; acc[4][1] += x1.x * b.y; acc[4][2] += x1.x * b.z; acc[4][3] += x1.x * b.w;
            acc[5][0] += x1.y * b.x; acc[5][1] += x1.y * b.y; acc[5][2] += x1.y * b.z; acc[5][3] += x1.y * b.w;
            acc[6][0] += x1.z * b.x; acc[6][1] += x1.z * b.y; acc[6][2] += x1.z * b.z; acc[6][3] += x1.z * b.w;
            acc[7][0] += x1.w * b.x; acc[7][1] += x1.w * b.y; acc[7][2] += x1.w * b.z; acc[7][3] += x1.w * b.w;
        }

        if (tile + 1 < nt) {
            __syncthreads();
            STAGE((tile + 1) & 1);
            __syncthreads();
        }
    }

    float bvals[4] = {0.f, 0.f, 0.f, 0.f};
    if (bias) {
#pragma unroll
        for (int j = 0; j < 4; j++) bvals[j] = bias[tx * 4 + j];
    }

#pragma unroll
    for (int r = 0; r < 8; r++) {
        int orow = bm0 + ty * 8 + r;
        if (orow < M) {
            float4 v;
            v.x = acc[r][0] + bvals[0];
            v.y = acc[r][1] + bvals[1];
            v.z = acc[r][2] + bvals[2];
            v.w = acc[r][3] + bvals[3];
            if (doRelu) {
                v.x = fmaxf(v.x, 0.f); v.y = fmaxf(v.y, 0.f);
                v.z = fmaxf(v.z, 0.f); v.w = fmaxf(v.w, 0.f);
            }
            *(float4*)(C + (size_t)orow * 64 + tx * 4) = v;
        }
    }
#undef FETCH
#undef STAGE
}

// ---------------- GCN layer 1: gather (warp per node), shuffle-batched indices ----------------
__global__ void gather1_kernel() {
    int gw = (blockIdx.x * blockDim.x + threadIdx.x) >> 5;
    int lane = threadIdx.x & 31;
    if (gw >= NN) return;
    int start = g_off[gw];
    int deg = g_icnt[gw];
    float a0 = 0.f, a1 = 0.f;
    for (int j0 = 0; j0 < deg; j0 += 32) {
        int n = min(32, deg - j0);
        int idx = 0; float w = 0.f;
        if (lane < n) { idx = g_csrc[start + j0 + lane]; w = g_onorm[idx]; }
#pragma unroll 4
        for (int jj = 0; jj < n; jj++) {
            int   s  = __shfl_sync(0xffffffffu, idx, jj);
            float wv = __shfl_sync(0xffffffffu, w, jj);
            const float* r = g_e0 + (size_t)s * 64;
            a0 += wv * r[lane];
            a1 += wv * r[lane + 32];
        }
    }
    float inn = g_innorm[gw];
    g_agg0[(size_t)gw * 64 + lane]      = a0 * inn;
    g_agg0[(size_t)gw * 64 + lane + 32] = a1 * inn;
}

// ---------------- GCN layer 2 + final combine fused ----------------
__global__ void gather2_final_kernel(const float* __restrict__ side, float* __restrict__ out) {
    int gw = (blockIdx.x * blockDim.x + threadIdx.x) >> 5;
    int lane = threadIdx.x & 31;
    if (gw >= NN) return;
    int start = g_off[gw];
    int deg = g_icnt[gw];
    float a0 = 0.f, a1 = 0.f;
    for (int j0 = 0; j0 < deg; j0 += 32) {
        int n = min(32, deg - j0);
        int idx = 0; float w = 0.f;
        if (lane < n) { idx = g_csrc[start + j0 + lane]; w = g_onorm[idx]; }
#pragma unroll 4
        for (int jj = 0; jj < n; jj++) {
            int   s  = __shfl_sync(0xffffffffu, idx, jj);
            float wv = __shfl_sync(0xffffffffu, w, jj);
            const float* r = g_agg0 + (size_t)s * 64;
            a0 += wv * r[lane];
            a1 += wv * r[lane + 32];
        }
    }
    float inn3 = g_innorm[gw] * (1.0f / 3.0f);
    size_t base = (size_t)gw * 64;
    float r0v = g_e0[base + lane]      + 0.5f * g_agg0[base + lane]      + inn3 * a0;
    float r1v = g_e0[base + lane + 32] + 0.5f * g_agg0[base + lane + 32] + inn3 * a1;
    if (gw >= NU) {
        size_t sb = (size_t)(gw - NU) * 64;
        r0v += side[sb + lane];
        r1v += side[sb + lane + 32];
    }
    out[base + lane]      = r0v;
    out[base + lane + 32] = r1v;
}

// ---------------- decode epilogue ----------------
__global__ void decode_kernel(const float* __restrict__ Tf, const float* __restrict__ Tcf,
                              const float* __restrict__ W1, const float* __restrict__ W2,
                              const int* __restrict__ userId, const int* __restrict__ posId,
                              const int* __restrict__ negId,
                              float* __restrict__ of, float* __restrict__ ocf) {
    __shared__ float w2s[64];
    __shared__ float w1l[64];
    int t = threadIdx.x;
    if (t < 64) {
        w2s[t] = W2[t];
        w1l[t] = W1[128 * 64 + t];
    }
    __syncthreads();

    int warp = t >> 5, lane = t & 31;
    int pair = blockIdx.x * 4 + warp;
    if (pair >= NP) return;

    int u  = userId[pair];
    int p  = posId[pair];
    int ng = negId[pair];

    float u0 = g_xu[(size_t)u * 64 + lane],   u1 = g_xu[(size_t)u * 64 + lane + 32];
    float p0 = g_xi[(size_t)p * 64 + lane],   p1 = g_xi[(size_t)p * 64 + lane + 32];
    float n0 = g_xi[(size_t)ng * 64 + lane],  n1 = g_xi[(size_t)ng * 64 + lane + 32];
    float wl0 = w1l[lane], wl1 = w1l[lane + 32];
    float w20 = w2s[lane], w21 = w2s[lane + 32];

    float tfp = Tf[pair],  tfn = Tf[pair + NP];
    float tcp = Tcf[pair], tcn = Tcf[pair + NP];

    auto combo = [&](float j0, float j1, float T) -> float {
        float x0 = u0 + j0 + T * wl0;
        float x1 = u1 + j1 + T * wl1;
        float e0 = x0 > 0.f ? x0 : (expf(x0) - 1.0f);
        float e1 = x1 > 0.f ? x1 : (expf(x1) - 1.0f);
        float s = e0 * w20 + e1 * w21;
        s += __shfl_down_sync(0xffffffffu, s, 16);
        s += __shfl_down_sync(0xffffffffu, s, 8);
        s += __shfl_down_sync(0xffffffffu, s, 4);
        s += __shfl_down_sync(0xffffffffu, s, 2);
        s += __shfl_down_sync(0xffffffffu, s, 1);
        return s;
    };

    float rf_p = combo(p0, p1, tfp);
    float rf_n = combo(n0, n1, tfn);
    float rc_p = combo(p0, p1, tcp);
    float rc_n = combo(n0, n1, tcn);

    if (lane == 0) {
        of[pair]       = rf_p;
        of[pair + NP]  = rf_n;
        ocf[pair]      = rc_p;
        ocf[pair + NP] = rc_n;
    }
}

// ---------------- launch ----------------
extern "C" void kernel_launch(void* const* d_in, const int* in_sizes, int n_in,
                              void* d_out, int out_size) {
    const float* userF = (const float*)d_in[0];
    const float* itemF = (const float*)d_in[1];
    const float* side  = (const float*)d_in[2];
    const float* Tf    = (const float*)d_in[3];
    const float* Tcf   = (const float*)d_in[4];
    const float* Wu    = (const float*)d_in[5];
    const float* bu    = (const float*)d_in[6];
    const float* Wi    = (const float*)d_in[7];
    const float* bi    = (const float*)d_in[8];
    const float* W1    = (const float*)d_in[9];
    const float* b1    = (const float*)d_in[10];
    const float* W2    = (const float*)d_in[11];
    const int* esrc    = (const int*)d_in[12];
    const int* edst    = (const int*)d_in[13];
    const int* userId  = (const int*)d_in[14];
    const int* posId   = (const int*)d_in[15];
    const int* negId   = (const int*)d_in[16];

    float* out   = (float*)d_out;
    float* outI  = out + (size_t)NU * H;
    float* outLF = out + (size_t)NN * H;
    float* outLC = outLF + 2 * NP;

    float *pe0, *pxu, *pxi;
    cudaGetSymbolAddress((void**)&pe0, g_e0);
    cudaGetSymbolAddress((void**)&pxu, g_xu);
    cudaGetSymbolAddress((void**)&pxi, g_xi);

    // CSR + norms
    clear_kernel<<<(NN + 255) / 256, 256>>>();
    degree_kernel<<<(NE + 255) / 256, 256>>>(esrc, edst);
    scan1_kernel<<<SCAN_NBLK, 1024>>>();
    scan2_kernel<<<1, 128>>>();
    scan3_kernel<<<(NN + 255) / 256, 256>>>();
    fill_kernel<<<(NE + 255) / 256, 256>>>(esrc, edst);

    // input embeddings (both GEMMs in one launch)
    int nb1 = (NU + 127) / 128;
    int nb2 = (NI + 127) / 128;
    gemm_dual<<<nb1 + nb2, 256>>>(userF, Wu, bu, pe0, NU,
                                  itemF, Wi, bi, pe0 + (size_t)NU * H, NI,
                                  128, 1, nb1);

    // GCN layers
    gather1_kernel<<<(NN * 32 + 255) / 256, 256>>>();
    gather2_final_kernel<<<(NN * 32 + 255) / 256, 256>>>(side, out);

    // per-node decode transforms (both in one launch)
    gemm_dual<<<nb1 + nb2, 256>>>(out,  W1,           b1,      pxu, NU,
                                  outI, W1 + 64 * 64, nullptr, pxi, NI,
                                  64, 0, nb1);

    // decode epilogue
    decode_kernel<<<(NP + 3) / 4, 128>>>(Tf, Tcf, W1, W2, userId, posId, negId, outLF, outLC);
}